// round 12
// baseline (speedup 1.0000x reference)
#include <cuda_runtime.h>
#include <cuda_bf16.h>
#include <mma.h>
#include <cstdint>
#include <math.h>

using namespace nvcuda;

#define BTCH 2
#define SEQ  2048
#define DIM  1024
#define NH   16
#define HDM  64
#define NTOK (BTCH*SEQ)

// ---------------- device global scratch (no allocs allowed) ----------------
__device__ float g_q[NTOK*DIM];
__device__ float g_k[NTOK*DIM];
__device__ float g_v[NTOK*DIM];
__device__ __nv_bfloat16 g_i0h[NTOK*DIM], g_i0l[NTOK*DIM];
__device__ __nv_bfloat16 g_i1h[NTOK*DIM], g_i1l[NTOK*DIM];
__device__ __nv_bfloat16 g_i2h[NTOK*DIM], g_i2l[NTOK*DIM];
__device__ __nv_bfloat16 g_w0h[DIM*DIM], g_w0l[DIM*DIM];
__device__ __nv_bfloat16 g_w1h[DIM*DIM], g_w1l[DIM*DIM];
__device__ __nv_bfloat16 g_w2h[DIM*DIM], g_w2l[DIM*DIM];
__device__ __nv_bfloat16 g_w3h[DIM*DIM], g_w3l[DIM*DIM];
__device__ __nv_bfloat16 g_ath[NTOK*DIM], g_atl[NTOK*DIM];

__device__ __forceinline__ uint2 pack4_bf16(float a, float b, float c, float d) {
    __nv_bfloat162 lo = __floats2bfloat162_rn(a, b);
    __nv_bfloat162 hi = __floats2bfloat162_rn(c, d);
    uint2 r;
    r.x = *reinterpret_cast<uint32_t*>(&lo);
    r.y = *reinterpret_cast<uint32_t*>(&hi);
    return r;
}

// FMA-pipe exp (no MUFU): exp(x) for x <= 0. ~1e-7 abs accuracy.
__device__ __forceinline__ float fast_exp(float x) {
    x = fmaxf(x, -80.f);
    float t = x * 1.4426950408889634f;           // x * log2(e)
    float z = t + 12582912.f;                    // 1.5*2^23 round-to-int trick
    float fn = z - 12582912.f;                   // rint(t)
    float f = t - fn;                            // f in [-0.5, 0.5]
    int n = __float_as_int(z);                   // low bits hold int(fn)
    float p = 0.0013333558f;
    p = fmaf(p, f, 0.0096181291f);
    p = fmaf(p, f, 0.0555041087f);
    p = fmaf(p, f, 0.2402264923f);
    p = fmaf(p, f, 0.6931471806f);
    p = fmaf(p, f, 1.0f);
    return __int_as_float(__float_as_int(p) + (n << 23));   // p * 2^fn
}

__device__ __forceinline__ void cp16(uint32_t dst, const void* src) {
    asm volatile("cp.async.cg.shared.global [%0], [%1], 16;"
                 :: "r"(dst), "l"(src) : "memory");
}
__device__ __forceinline__ void cp_commit() {
    asm volatile("cp.async.commit_group;" ::: "memory");
}
__device__ __forceinline__ void cp_wait1() {
    asm volatile("cp.async.wait_group 1;" ::: "memory");
}
__device__ __forceinline__ void cp_wait0() {
    asm volatile("cp.async.wait_group 0;" ::: "memory");
}

// ---------------------------------------------------------------------------
// fp32 -> bf16 hi/lo split, 4 elements/thread. Up to 4 tensors via grid.z.
// ---------------------------------------------------------------------------
struct Split4 {
    const float* s[4];
    __nv_bfloat16* h[4];
    __nv_bfloat16* l[4];
};
__global__ void splitk(Split4 a) {
    int z = blockIdx.z;
    size_t i = ((size_t)blockIdx.x * blockDim.x + threadIdx.x) * 4;
    float4 v = *(const float4*)(a.s[z] + i);
    float hx = __bfloat162float(__float2bfloat16(v.x));
    float hy = __bfloat162float(__float2bfloat16(v.y));
    float hz = __bfloat162float(__float2bfloat16(v.z));
    float hw = __bfloat162float(__float2bfloat16(v.w));
    *(uint2*)(a.h[z] + i) = pack4_bf16(hx, hy, hz, hw);
    *(uint2*)(a.l[z] + i) = pack4_bf16(v.x - hx, v.y - hy, v.z - hz, v.w - hw);
}

// ---------------------------------------------------------------------------
// bf16 WMMA GEMM + bias, 3x compensation, cp.async double buffer.
// ---------------------------------------------------------------------------
struct GemmArgs {
    const __nv_bfloat16 *ah[3], *al[3], *wh[3], *wl[3];
    const float* bias[3];
    float* c[3];
};

#define STAGE_BYTES 41984
#define OFF_AL 12288
#define OFF_BH 24576
#define OFF_BL 33280
#define GEMM_SMEM (2*STAGE_BYTES + 8192)

__global__ __launch_bounds__(256, 2)
void gemm_bf3(GemmArgs g) {
    extern __shared__ __align__(16) char sm[];
    int z = blockIdx.z;
    const __nv_bfloat16* Ahg = g.ah[z];
    const __nv_bfloat16* Alg = g.al[z];
    const __nv_bfloat16* Whg = g.wh[z];
    const __nv_bfloat16* Wlg = g.wl[z];
    const float* bias = g.bias[z];
    float* C = g.c[z];

    int tid  = threadIdx.x;
    int warp = tid >> 5;
    int wm   = warp >> 1;
    int wn   = warp & 1;
    int m0 = blockIdx.y * 128;
    int n0 = blockIdx.x * 128;

    uint32_t sbase = (uint32_t)__cvta_generic_to_shared(sm);
    float* biasS = (float*)(sm + 2 * STAGE_BYTES);

    auto stage_load = [&](int st, int c) {
        uint32_t b = sbase + st * STAGE_BYTES;
        #pragma unroll
        for (int r = 0; r < 2; r++) {
            int id = r * 256 + tid;
            int row = id >> 2, c4 = id & 3;
            size_t off = (size_t)(m0 + row) * DIM + c * 32 + c4 * 8;
            cp16(b + row * 96 + c4 * 16, Ahg + off);
            cp16(b + OFF_AL + row * 96 + c4 * 16, Alg + off);
        }
        #pragma unroll
        for (int r = 0; r < 2; r++) {
            int id = r * 256 + tid;
            int row = id >> 4, c4 = id & 15;
            size_t off = (size_t)(c * 32 + row) * DIM + n0 + c4 * 8;
            cp16(b + OFF_BH + row * 272 + c4 * 16, Whg + off);
            cp16(b + OFF_BL + row * 272 + c4 * 16, Wlg + off);
        }
    };

    for (int i = tid; i < 16 * 128; i += 256)
        biasS[i] = bias[n0 + (i & 127)];

    stage_load(0, 0);
    cp_commit();
    __syncthreads();

    wmma::fragment<wmma::accumulator, 16, 16, 16, float> acc[2][4];
    #pragma unroll
    for (int mi = 0; mi < 2; mi++)
        #pragma unroll
        for (int ni = 0; ni < 4; ni++)
            wmma::load_matrix_sync(acc[mi][ni], biasS + wn * 64 + ni * 16,
                                   128, wmma::mem_row_major);

    for (int c = 0; c < 32; c++) {
        if (c < 31) {
            stage_load((c + 1) & 1, c + 1);
            cp_commit();
            cp_wait1();
        } else {
            cp_wait0();
        }
        __syncthreads();

        const char* sb = sm + (c & 1) * STAGE_BYTES;
        const __nv_bfloat16* sAh = (const __nv_bfloat16*)sb;
        const __nv_bfloat16* sAl = (const __nv_bfloat16*)(sb + OFF_AL);
        const __nv_bfloat16* sBh = (const __nv_bfloat16*)(sb + OFF_BH);
        const __nv_bfloat16* sBl = (const __nv_bfloat16*)(sb + OFF_BL);

        #pragma unroll
        for (int kk = 0; kk < 2; kk++) {
            wmma::fragment<wmma::matrix_a, 16, 16, 16, __nv_bfloat16, wmma::row_major> ah[2], al[2];
            #pragma unroll
            for (int mi = 0; mi < 2; mi++) {
                wmma::load_matrix_sync(ah[mi], sAh + (wm*32 + mi*16) * 48 + kk*16, 48);
                wmma::load_matrix_sync(al[mi], sAl + (wm*32 + mi*16) * 48 + kk*16, 48);
            }
            #pragma unroll
            for (int ni = 0; ni < 4; ni++) {
                wmma::fragment<wmma::matrix_b, 16, 16, 16, __nv_bfloat16, wmma::row_major> bh, bl;
                wmma::load_matrix_sync(bh, sBh + (kk*16) * 136 + wn*64 + ni*16, 136);
                wmma::load_matrix_sync(bl, sBl + (kk*16) * 136 + wn*64 + ni*16, 136);
                #pragma unroll
                for (int mi = 0; mi < 2; mi++) {
                    wmma::mma_sync(acc[mi][ni], ah[mi], bh, acc[mi][ni]);
                    wmma::mma_sync(acc[mi][ni], ah[mi], bl, acc[mi][ni]);
                    wmma::mma_sync(acc[mi][ni], al[mi], bh, acc[mi][ni]);
                }
            }
        }
        __syncthreads();
    }

    #pragma unroll
    for (int mi = 0; mi < 2; mi++)
        #pragma unroll
        for (int ni = 0; ni < 4; ni++)
            wmma::store_matrix_sync(
                C + (size_t)(m0 + wm*32 + mi*16) * DIM + n0 + wn*64 + ni*16,
                acc[mi][ni], DIM, wmma::mem_row_major);
}

// ---------------------------------------------------------------------------
// Flash attention: fp32, but exp on the FMA pipe (fast_exp) and Q pre-scaled.
// ---------------------------------------------------------------------------
__global__ __launch_bounds__(256, 4)
void flash_attn(const float* __restrict__ Qg, const float* __restrict__ Kg,
                const float* __restrict__ Vg,
                __nv_bfloat16* __restrict__ Oh, __nv_bfloat16* __restrict__ Ol) {
    __shared__ float Qs[64][64];
    __shared__ float KsPs[64*64];
    __shared__ float Vs[64][64];

    int tid = threadIdx.x;
    int ty = tid >> 4, tx = tid & 15;
    int bh = blockIdx.y;
    int b = bh / NH, h = bh % NH;
    int q0 = blockIdx.x * 64;

    const float scale = 0.125f;

    {
        const float* Qp = Qg + (size_t)(b*SEQ + q0) * DIM + h*HDM;
        #pragma unroll
        for (int it = 0; it < 4; it++) {
            int idx4 = tid + it * 256;
            int r = idx4 >> 4;
            int cc = (idx4 & 15) * 4;
            float4 v = *(const float4*)&Qp[(size_t)r * DIM + cc];
            Qs[cc+0][r] = v.x * scale; Qs[cc+1][r] = v.y * scale;
            Qs[cc+2][r] = v.z * scale; Qs[cc+3][r] = v.w * scale;
        }
    }

    float o[4][4];
    float m_i[4], l_i[4];
    #pragma unroll
    for (int i = 0; i < 4; i++) {
        m_i[i] = -1e30f; l_i[i] = 0.f;
        #pragma unroll
        for (int j = 0; j < 4; j++) o[i][j] = 0.f;
    }

    for (int k0 = 0; k0 < SEQ; k0 += 64) {
        __syncthreads();
        {
            const float* Kp = Kg + (size_t)(b*SEQ + k0) * DIM + h*HDM;
            const float* Vp = Vg + (size_t)(b*SEQ + k0) * DIM + h*HDM;
            #pragma unroll
            for (int it = 0; it < 4; it++) {
                int idx4 = tid + it * 256;
                int r = idx4 >> 4;
                int cc = (idx4 & 15) * 4;
                float4 vk = *(const float4*)&Kp[(size_t)r * DIM + cc];
                KsPs[(cc+0)*64 + r] = vk.x; KsPs[(cc+1)*64 + r] = vk.y;
                KsPs[(cc+2)*64 + r] = vk.z; KsPs[(cc+3)*64 + r] = vk.w;
                float4 vv = *(const float4*)&Vp[(size_t)r * DIM + cc];
                *(float4*)&Vs[r][cc] = vv;
            }
        }
        __syncthreads();

        float s[4][4];
        #pragma unroll
        for (int i = 0; i < 4; i++)
            #pragma unroll
            for (int j = 0; j < 4; j++) s[i][j] = 0.f;

        #pragma unroll 8
        for (int kk = 0; kk < 64; kk++) {
            float4 q4 = *(float4*)&Qs[kk][ty*4];
            float4 k4 = *(float4*)&KsPs[kk*64 + tx*4];
            float qv[4] = {q4.x, q4.y, q4.z, q4.w};
            float kv[4] = {k4.x, k4.y, k4.z, k4.w};
            #pragma unroll
            for (int i = 0; i < 4; i++)
                #pragma unroll
                for (int j = 0; j < 4; j++)
                    s[i][j] += qv[i] * kv[j];
        }

        // Online softmax per row (scores already scaled via Q)
        #pragma unroll
        for (int i = 0; i < 4; i++) {
            float tm = s[i][0];
            #pragma unroll
            for (int j = 1; j < 4; j++) tm = fmaxf(tm, s[i][j]);
            #pragma unroll
            for (int d = 1; d < 16; d <<= 1)
                tm = fmaxf(tm, __shfl_xor_sync(0xffffffffu, tm, d));
            float mnew = fmaxf(m_i[i], tm);
            float corr = fast_exp(m_i[i] - mnew);
            m_i[i] = mnew;
            float rs = 0.f;
            #pragma unroll
            for (int j = 0; j < 4; j++) {
                float p = fast_exp(s[i][j] - mnew);
                s[i][j] = p;
                rs += p;
            }
            #pragma unroll
            for (int d = 1; d < 16; d <<= 1)
                rs += __shfl_xor_sync(0xffffffffu, rs, d);
            l_i[i] = l_i[i] * corr + rs;
            #pragma unroll
            for (int j = 0; j < 4; j++) o[i][j] *= corr;
        }

        __syncthreads();
        #pragma unroll
        for (int i = 0; i < 4; i++) {
            float4 pv = make_float4(s[i][0], s[i][1], s[i][2], s[i][3]);
            *(float4*)&KsPs[(ty*4 + i)*64 + tx*4] = pv;
        }
        __syncthreads();

        #pragma unroll 8
        for (int kk = 0; kk < 64; kk++) {
            float4 v4 = *(float4*)&Vs[kk][tx*4];
            float vv[4] = {v4.x, v4.y, v4.z, v4.w};
            #pragma unroll
            for (int i = 0; i < 4; i++) {
                float p = KsPs[(ty*4 + i)*64 + kk];
                #pragma unroll
                for (int j = 0; j < 4; j++)
                    o[i][j] += p * vv[j];
            }
        }
    }

    #pragma unroll
    for (int i = 0; i < 4; i++) {
        float inv = 1.f / l_i[i];
        int row = b*SEQ + q0 + ty*4 + i;
        size_t base = (size_t)row * DIM + h*HDM + tx*4;
        float rx = o[i][0]*inv, ry = o[i][1]*inv, rz = o[i][2]*inv, rw = o[i][3]*inv;
        float hx = __bfloat162float(__float2bfloat16(rx));
        float hy = __bfloat162float(__float2bfloat16(ry));
        float hz = __bfloat162float(__float2bfloat16(rz));
        float hw = __bfloat162float(__float2bfloat16(rw));
        *(uint2*)&Oh[base] = pack4_bf16(hx, hy, hz, hw);
        *(uint2*)&Ol[base] = pack4_bf16(rx - hx, ry - hy, rz - hz, rw - hw);
    }
}

extern "C" void kernel_launch(void* const* d_in, const int* in_sizes, int n_in,
                              void* d_out, int out_size) {
    const float* query = (const float*)d_in[0];
    const float* key   = (const float*)d_in[1];
    const float* value = (const float*)d_in[2];
    const float* Wq = (const float*)d_in[3];
    const float* bq = (const float*)d_in[4];
    const float* Wk = (const float*)d_in[5];
    const float* bk = (const float*)d_in[6];
    const float* Wv = (const float*)d_in[7];
    const float* bv = (const float*)d_in[8];
    const float* Wo = (const float*)d_in[9];
    const float* bo = (const float*)d_in[10];
    float* out = (float*)d_out;

    float *gq, *gk, *gv;
    __nv_bfloat16 *i0h,*i0l,*i1h,*i1l,*i2h,*i2l;
    __nv_bfloat16 *w0h,*w0l,*w1h,*w1l,*w2h,*w2l,*w3h,*w3l,*ath,*atl;
    cudaGetSymbolAddress((void**)&gq, g_q);
    cudaGetSymbolAddress((void**)&gk, g_k);
    cudaGetSymbolAddress((void**)&gv, g_v);
    cudaGetSymbolAddress((void**)&i0h, g_i0h); cudaGetSymbolAddress((void**)&i0l, g_i0l);
    cudaGetSymbolAddress((void**)&i1h, g_i1h); cudaGetSymbolAddress((void**)&i1l, g_i1l);
    cudaGetSymbolAddress((void**)&i2h, g_i2h); cudaGetSymbolAddress((void**)&i2l, g_i2l);
    cudaGetSymbolAddress((void**)&w0h, g_w0h); cudaGetSymbolAddress((void**)&w0l, g_w0l);
    cudaGetSymbolAddress((void**)&w1h, g_w1h); cudaGetSymbolAddress((void**)&w1l, g_w1l);
    cudaGetSymbolAddress((void**)&w2h, g_w2h); cudaGetSymbolAddress((void**)&w2l, g_w2l);
    cudaGetSymbolAddress((void**)&w3h, g_w3h); cudaGetSymbolAddress((void**)&w3l, g_w3l);
    cudaGetSymbolAddress((void**)&ath, g_ath); cudaGetSymbolAddress((void**)&atl, g_atl);

    cudaFuncSetAttribute(gemm_bf3, cudaFuncAttributeMaxDynamicSharedMemorySize,
                         GEMM_SMEM);

    Split4 sa;
    sa.s[0] = query; sa.h[0] = i0h; sa.l[0] = i0l;
    sa.s[1] = key;   sa.h[1] = i1h; sa.l[1] = i1l;
    sa.s[2] = value; sa.h[2] = i2h; sa.l[2] = i2l;
    sa.s[3] = query; sa.h[3] = i0h; sa.l[3] = i0l;  // unused
    splitk<<<dim3(NTOK*DIM/1024, 1, 3), 256>>>(sa);

    Split4 sw;
    sw.s[0] = Wq; sw.h[0] = w0h; sw.l[0] = w0l;
    sw.s[1] = Wk; sw.h[1] = w1h; sw.l[1] = w1l;
    sw.s[2] = Wv; sw.h[2] = w2h; sw.l[2] = w2l;
    sw.s[3] = Wo; sw.h[3] = w3h; sw.l[3] = w3l;
    splitk<<<dim3(DIM*DIM/1024, 1, 4), 256>>>(sw);

    GemmArgs gqkv;
    gqkv.ah[0]=i0h; gqkv.al[0]=i0l; gqkv.wh[0]=w0h; gqkv.wl[0]=w0l; gqkv.bias[0]=bq; gqkv.c[0]=gq;
    gqkv.ah[1]=i1h; gqkv.al[1]=i1l; gqkv.wh[1]=w1h; gqkv.wl[1]=w1l; gqkv.bias[1]=bk; gqkv.c[1]=gk;
    gqkv.ah[2]=i2h; gqkv.al[2]=i2l; gqkv.wh[2]=w2h; gqkv.wl[2]=w2l; gqkv.bias[2]=bv; gqkv.c[2]=gv;
    gemm_bf3<<<dim3(DIM/128, NTOK/128, 3), 256, GEMM_SMEM>>>(gqkv);

    flash_attn<<<dim3(SEQ/64, BTCH*NH), 256>>>(gq, gk, gv, ath, atl);

    GemmArgs go;
    go.ah[0]=ath; go.al[0]=atl; go.wh[0]=w3h; go.wl[0]=w3l; go.bias[0]=bo; go.c[0]=out;
    go.ah[1]=ath; go.al[1]=atl; go.wh[1]=w3h; go.wl[1]=w3l; go.bias[1]=bo; go.c[1]=out;
    go.ah[2]=ath; go.al[2]=atl; go.wh[2]=w3h; go.wl[2]=w3l; go.bias[2]=bo; go.c[2]=out;
    gemm_bf3<<<dim3(DIM/128, NTOK/128, 1), 256, GEMM_SMEM>>>(go);
}

// round 13
// speedup vs baseline: 1.9716x; 1.9716x over previous
#include <cuda_runtime.h>
#include <cuda_bf16.h>
#include <mma.h>
#include <cstdint>
#include <math.h>

using namespace nvcuda;

#define BTCH 2
#define SEQ  2048
#define DIM  1024
#define NH   16
#define HDM  64
#define NTOK (BTCH*SEQ)

// ---------------- device global scratch (no allocs allowed) ----------------
__device__ __nv_bfloat16 g_i0h[NTOK*DIM], g_i0l[NTOK*DIM];
__device__ __nv_bfloat16 g_i1h[NTOK*DIM], g_i1l[NTOK*DIM];
__device__ __nv_bfloat16 g_i2h[NTOK*DIM], g_i2l[NTOK*DIM];
__device__ __nv_bfloat16 g_w0h[DIM*DIM], g_w0l[DIM*DIM];
__device__ __nv_bfloat16 g_w1h[DIM*DIM], g_w1l[DIM*DIM];
__device__ __nv_bfloat16 g_w2h[DIM*DIM], g_w2l[DIM*DIM];
__device__ __nv_bfloat16 g_w3h[DIM*DIM], g_w3l[DIM*DIM];
__device__ __nv_bfloat16 g_qh[NTOK*DIM], g_ql[NTOK*DIM];
__device__ __nv_bfloat16 g_kh[NTOK*DIM], g_kl[NTOK*DIM];
__device__ __nv_bfloat16 g_vh[NTOK*DIM], g_vl[NTOK*DIM];
__device__ __nv_bfloat16 g_ath[NTOK*DIM], g_atl[NTOK*DIM];

__device__ __forceinline__ uint2 pack4_bf16(float a, float b, float c, float d) {
    __nv_bfloat162 lo = __floats2bfloat162_rn(a, b);
    __nv_bfloat162 hi = __floats2bfloat162_rn(c, d);
    uint2 r;
    r.x = *reinterpret_cast<uint32_t*>(&lo);
    r.y = *reinterpret_cast<uint32_t*>(&hi);
    return r;
}

// FMA-pipe exp: exp(x) for x <= 0. ~1e-7 abs accuracy.
__device__ __forceinline__ float fast_exp(float x) {
    x = fmaxf(x, -80.f);
    float t = x * 1.4426950408889634f;
    float z = t + 12582912.f;
    float fn = z - 12582912.f;
    float f = t - fn;
    int n = __float_as_int(z);
    float p = 0.0013333558f;
    p = fmaf(p, f, 0.0096181291f);
    p = fmaf(p, f, 0.0555041087f);
    p = fmaf(p, f, 0.2402264923f);
    p = fmaf(p, f, 0.6931471806f);
    p = fmaf(p, f, 1.0f);
    return __int_as_float(__float_as_int(p) + (n << 23));
}

__device__ __forceinline__ void cp16(uint32_t dst, const void* src) {
    asm volatile("cp.async.cg.shared.global [%0], [%1], 16;"
                 :: "r"(dst), "l"(src) : "memory");
}
__device__ __forceinline__ void cp_commit() {
    asm volatile("cp.async.commit_group;" ::: "memory");
}
__device__ __forceinline__ void cp_wait1() {
    asm volatile("cp.async.wait_group 1;" ::: "memory");
}
__device__ __forceinline__ void cp_wait0() {
    asm volatile("cp.async.wait_group 0;" ::: "memory");
}

__device__ __forceinline__ void mma16816(float* d, const uint32_t* a,
                                         const uint32_t* b, const float* c) {
    asm volatile("mma.sync.aligned.m16n8k16.row.col.f32.bf16.bf16.f32 "
        "{%0,%1,%2,%3}, {%4,%5,%6,%7}, {%8,%9}, {%10,%11,%12,%13};"
        : "=f"(d[0]),"=f"(d[1]),"=f"(d[2]),"=f"(d[3])
        : "r"(a[0]),"r"(a[1]),"r"(a[2]),"r"(a[3]), "r"(b[0]),"r"(b[1]),
          "f"(c[0]),"f"(c[1]),"f"(c[2]),"f"(c[3]));
}
__device__ __forceinline__ void ldsm4(uint32_t* r, uint32_t addr) {
    asm volatile("ldmatrix.sync.aligned.m8n8.x4.shared.b16 {%0,%1,%2,%3}, [%4];"
        : "=r"(r[0]),"=r"(r[1]),"=r"(r[2]),"=r"(r[3]) : "r"(addr));
}
__device__ __forceinline__ void ldsm4t(uint32_t* r, uint32_t addr) {
    asm volatile("ldmatrix.sync.aligned.m8n8.x4.trans.shared.b16 {%0,%1,%2,%3}, [%4];"
        : "=r"(r[0]),"=r"(r[1]),"=r"(r[2]),"=r"(r[3]) : "r"(addr));
}
// split pair of floats into bf16 hi (packed) and bf16 lo (packed)
__device__ __forceinline__ void split2(float x, float y, uint32_t& h, uint32_t& l) {
    __nv_bfloat162 hh = __floats2bfloat162_rn(x, y);
    float hx = __bfloat162float(hh.x), hy = __bfloat162float(hh.y);
    __nv_bfloat162 ll = __floats2bfloat162_rn(x - hx, y - hy);
    h = *reinterpret_cast<uint32_t*>(&hh);
    l = *reinterpret_cast<uint32_t*>(&ll);
}

// ---------------------------------------------------------------------------
// fp32 -> bf16 hi/lo split (activations + weights)
// ---------------------------------------------------------------------------
struct Split4 {
    const float* s[4];
    __nv_bfloat16* h[4];
    __nv_bfloat16* l[4];
};
__global__ void splitk(Split4 a) {
    int z = blockIdx.z;
    size_t i = ((size_t)blockIdx.x * blockDim.x + threadIdx.x) * 4;
    float4 v = *(const float4*)(a.s[z] + i);
    float hx = __bfloat162float(__float2bfloat16(v.x));
    float hy = __bfloat162float(__float2bfloat16(v.y));
    float hz = __bfloat162float(__float2bfloat16(v.z));
    float hw = __bfloat162float(__float2bfloat16(v.w));
    *(uint2*)(a.h[z] + i) = pack4_bf16(hx, hy, hz, hw);
    *(uint2*)(a.l[z] + i) = pack4_bf16(v.x - hx, v.y - hy, v.z - hz, v.w - hw);
}

// ---------------------------------------------------------------------------
// bf16 WMMA GEMM + bias, 3x comp, cp.async double buffer.
// Epilogue: if ch[z] != null -> scale + bf16 hi/lo store; else fp32 store.
// ---------------------------------------------------------------------------
struct GemmArgs {
    const __nv_bfloat16 *ah[3], *al[3], *wh[3], *wl[3];
    const float* bias[3];
    float* c[3];
    __nv_bfloat16 *ch[3], *cl[3];
    float scale[3];
};

#define STAGE_BYTES 41984
#define OFF_AL 12288
#define OFF_BH 24576
#define OFF_BL 33280
#define GEMM_SMEM (2*STAGE_BYTES + 8192)

__global__ __launch_bounds__(256, 2)
void gemm_bf3(GemmArgs g) {
    extern __shared__ __align__(16) char sm[];
    int z = blockIdx.z;
    const __nv_bfloat16* Ahg = g.ah[z];
    const __nv_bfloat16* Alg = g.al[z];
    const __nv_bfloat16* Whg = g.wh[z];
    const __nv_bfloat16* Wlg = g.wl[z];
    const float* bias = g.bias[z];

    int tid  = threadIdx.x;
    int warp = tid >> 5;
    int lane = tid & 31;
    int wm   = warp >> 1;
    int wn   = warp & 1;
    int m0 = blockIdx.y * 128;
    int n0 = blockIdx.x * 128;

    uint32_t sbase = (uint32_t)__cvta_generic_to_shared(sm);
    float* biasS = (float*)(sm + 2 * STAGE_BYTES);

    auto stage_load = [&](int st, int c) {
        uint32_t b = sbase + st * STAGE_BYTES;
        #pragma unroll
        for (int r = 0; r < 2; r++) {
            int id = r * 256 + tid;
            int row = id >> 2, c4 = id & 3;
            size_t off = (size_t)(m0 + row) * DIM + c * 32 + c4 * 8;
            cp16(b + row * 96 + c4 * 16, Ahg + off);
            cp16(b + OFF_AL + row * 96 + c4 * 16, Alg + off);
        }
        #pragma unroll
        for (int r = 0; r < 2; r++) {
            int id = r * 256 + tid;
            int row = id >> 4, c4 = id & 15;
            size_t off = (size_t)(c * 32 + row) * DIM + n0 + c4 * 8;
            cp16(b + OFF_BH + row * 272 + c4 * 16, Whg + off);
            cp16(b + OFF_BL + row * 272 + c4 * 16, Wlg + off);
        }
    };

    for (int i = tid; i < 16 * 128; i += 256)
        biasS[i] = bias[n0 + (i & 127)];

    stage_load(0, 0);
    cp_commit();
    __syncthreads();

    wmma::fragment<wmma::accumulator, 16, 16, 16, float> acc[2][4];
    #pragma unroll
    for (int mi = 0; mi < 2; mi++)
        #pragma unroll
        for (int ni = 0; ni < 4; ni++)
            wmma::load_matrix_sync(acc[mi][ni], biasS + wn * 64 + ni * 16,
                                   128, wmma::mem_row_major);

    for (int c = 0; c < 32; c++) {
        if (c < 31) {
            stage_load((c + 1) & 1, c + 1);
            cp_commit();
            cp_wait1();
        } else {
            cp_wait0();
        }
        __syncthreads();

        const char* sb = sm + (c & 1) * STAGE_BYTES;
        const __nv_bfloat16* sAh = (const __nv_bfloat16*)sb;
        const __nv_bfloat16* sAl = (const __nv_bfloat16*)(sb + OFF_AL);
        const __nv_bfloat16* sBh = (const __nv_bfloat16*)(sb + OFF_BH);
        const __nv_bfloat16* sBl = (const __nv_bfloat16*)(sb + OFF_BL);

        #pragma unroll
        for (int kk = 0; kk < 2; kk++) {
            wmma::fragment<wmma::matrix_a, 16, 16, 16, __nv_bfloat16, wmma::row_major> ah[2], al[2];
            #pragma unroll
            for (int mi = 0; mi < 2; mi++) {
                wmma::load_matrix_sync(ah[mi], sAh + (wm*32 + mi*16) * 48 + kk*16, 48);
                wmma::load_matrix_sync(al[mi], sAl + (wm*32 + mi*16) * 48 + kk*16, 48);
            }
            #pragma unroll
            for (int ni = 0; ni < 4; ni++) {
                wmma::fragment<wmma::matrix_b, 16, 16, 16, __nv_bfloat16, wmma::row_major> bh, bl;
                wmma::load_matrix_sync(bh, sBh + (kk*16) * 136 + wn*64 + ni*16, 136);
                wmma::load_matrix_sync(bl, sBl + (kk*16) * 136 + wn*64 + ni*16, 136);
                #pragma unroll
                for (int mi = 0; mi < 2; mi++) {
                    wmma::mma_sync(acc[mi][ni], ah[mi], bh, acc[mi][ni]);
                    wmma::mma_sync(acc[mi][ni], ah[mi], bl, acc[mi][ni]);
                    wmma::mma_sync(acc[mi][ni], al[mi], bh, acc[mi][ni]);
                }
            }
        }
        __syncthreads();
    }

    if (g.ch[z]) {
        __nv_bfloat16* CH = g.ch[z];
        __nv_bfloat16* CL = g.cl[z];
        float sc = g.scale[z];
        float* scr = (float*)(sm + 1024 * warp);   // 256 f32 per warp
        #pragma unroll
        for (int mi = 0; mi < 2; mi++)
            #pragma unroll
            for (int ni = 0; ni < 4; ni++) {
                __syncwarp();
                wmma::store_matrix_sync(scr, acc[mi][ni], 16, wmma::mem_row_major);
                __syncwarp();
                float4 v0 = *(float4*)&scr[lane * 8];
                float4 v1 = *(float4*)&scr[lane * 8 + 4];
                v0.x *= sc; v0.y *= sc; v0.z *= sc; v0.w *= sc;
                v1.x *= sc; v1.y *= sc; v1.z *= sc; v1.w *= sc;
                uint32_t h0,l0u,h1,l1u,h2,l2u,h3,l3u;
                split2(v0.x, v0.y, h0, l0u);
                split2(v0.z, v0.w, h1, l1u);
                split2(v1.x, v1.y, h2, l2u);
                split2(v1.z, v1.w, h3, l3u);
                int row = m0 + wm*32 + mi*16 + (lane >> 1);
                int col = n0 + wn*64 + ni*16 + (lane & 1) * 8;
                size_t go = (size_t)row * DIM + col;
                uint4 uh = make_uint4(h0, h1, h2, h3);
                uint4 ul = make_uint4(l0u, l1u, l2u, l3u);
                *(uint4*)&CH[go] = uh;
                *(uint4*)&CL[go] = ul;
            }
    } else {
        float* C = g.c[z];
        #pragma unroll
        for (int mi = 0; mi < 2; mi++)
            #pragma unroll
            for (int ni = 0; ni < 4; ni++)
                wmma::store_matrix_sync(
                    C + (size_t)(m0 + wm*32 + mi*16) * DIM + n0 + wn*64 + ni*16,
                    acc[mi][ni], DIM, wmma::mem_row_major);
    }
}

// ---------------------------------------------------------------------------
// FlashAttention-2 style mma.sync bf16 flash with hi/lo compensation.
// Q-tile 128 (8 warps x 16 rows), K-tile 64, HD 64. Online softmax in regs.
// ---------------------------------------------------------------------------
#define QT 128
#define KT 64
#define LDT 72                    // padded row (elems) to kill ldmatrix conflicts
#define TILE_E (KT*LDT)           // elems per K/V tile
#define STAGE_E (4*TILE_E)        // Kh,Kl,Vh,Vl
#define FLASH_SMEM (2*STAGE_E*2)  // 2 stages, bytes = 73728

__global__ __launch_bounds__(256, 2)
void flash_mma(const __nv_bfloat16* __restrict__ Qh_g, const __nv_bfloat16* __restrict__ Ql_g,
               const __nv_bfloat16* __restrict__ Kh_g, const __nv_bfloat16* __restrict__ Kl_g,
               const __nv_bfloat16* __restrict__ Vh_g, const __nv_bfloat16* __restrict__ Vl_g,
               __nv_bfloat16* __restrict__ Oh_g, __nv_bfloat16* __restrict__ Ol_g) {
    extern __shared__ __align__(16) char sm[];
    __nv_bfloat16* smb = (__nv_bfloat16*)sm;
    uint32_t sb = (uint32_t)__cvta_generic_to_shared(sm);

    int tid = threadIdx.x, lane = tid & 31, warp = tid >> 5;
    int bh = blockIdx.y, b = bh >> 4, h = bh & 15;
    int q0 = blockIdx.x * QT;

    auto stage_load = [&](int st, int t) {
        uint32_t base = sb + st * STAGE_E * 2;
        #pragma unroll
        for (int it2 = 0; it2 < 2; it2++) {
            int rem = it2 * 256 + tid;           // 0..511
            int r = rem >> 3, c8 = rem & 7;
            size_t gg = (size_t)(b*SEQ + t*KT + r) * DIM + h*HDM + c8*8;
            uint32_t so = (uint32_t)(r*LDT + c8*8) * 2;
            cp16(base + 0*TILE_E*2 + so, Kh_g + gg);
            cp16(base + 1*TILE_E*2 + so, Kl_g + gg);
            cp16(base + 2*TILE_E*2 + so, Vh_g + gg);
            cp16(base + 3*TILE_E*2 + so, Vl_g + gg);
        }
    };

    // prefetch k-tile 0 into stage 0 (async) while staging Q in stage 1 area
    stage_load(0, 0);
    cp_commit();
    {
        __nv_bfloat16* qs = smb + STAGE_E;       // stage-1 region
        #pragma unroll
        for (int it = 0; it < 4; it++) {
            int id = it * 256 + tid;             // 0..1023
            int r = id >> 3, c8 = id & 7;
            size_t gg = (size_t)(b*SEQ + q0 + r) * DIM + h*HDM + c8*8;
            *(uint4*)&qs[r*LDT + c8*8]           = *(const uint4*)&Qh_g[gg];
            *(uint4*)&qs[QT*LDT + r*LDT + c8*8]  = *(const uint4*)&Ql_g[gg];
        }
    }
    __syncthreads();

    // Q fragments (A, 16x16), 4 hd-chunks, hi+lo
    uint32_t qh[4][4], ql[4][4];
    {
        uint32_t qb = sb + STAGE_E * 2;
        int rr = warp*16 + (lane & 15);
        int cc = (lane >> 4) * 8;
        #pragma unroll
        for (int kc = 0; kc < 4; kc++) {
            ldsm4(qh[kc], qb + (uint32_t)(rr*LDT + kc*16 + cc) * 2);
            ldsm4(ql[kc], qb + (uint32_t)(QT*LDT + rr*LDT + kc*16 + cc) * 2);
        }
    }

    float oacc[8][4];
    #pragma unroll
    for (int u = 0; u < 8; u++)
        #pragma unroll
        for (int e = 0; e < 4; e++) oacc[u][e] = 0.f;
    float m0 = -1e30f, m1 = -1e30f, l0 = 0.f, l1 = 0.f;

    for (int t = 0; t < SEQ/KT; t++) {
        __syncthreads();                          // done reading buffer being overwritten
        if (t < SEQ/KT - 1) {
            stage_load((t + 1) & 1, t + 1);
            cp_commit();
            cp_wait1();
        } else {
            cp_wait0();
        }
        __syncthreads();

        uint32_t kb  = sb + (uint32_t)((t & 1) * STAGE_E) * 2;
        uint32_t khb = kb, klb = kb + TILE_E*2;
        uint32_t vhb = kb + 2*TILE_E*2, vlb = kb + 3*TILE_E*2;

        // ---- S = Q K^T (3x comp) ----
        float s[8][4];
        #pragma unroll
        for (int j = 0; j < 8; j++)
            #pragma unroll
            for (int e = 0; e < 4; e++) s[j][e] = 0.f;

        #pragma unroll
        for (int kc = 0; kc < 4; kc++) {
            #pragma unroll
            for (int t2 = 0; t2 < 4; t2++) {
                uint32_t kh[4], kl[4];
                uint32_t ka = (uint32_t)(((16*t2 + (lane>>4)*8 + (lane&7)) * LDT
                              + kc*16 + ((lane>>3)&1)*8) * 2);
                ldsm4(kh, khb + ka);
                ldsm4(kl, klb + ka);
                mma16816(s[2*t2],   qh[kc], &kh[0], s[2*t2]);
                mma16816(s[2*t2],   qh[kc], &kl[0], s[2*t2]);
                mma16816(s[2*t2],   ql[kc], &kh[0], s[2*t2]);
                mma16816(s[2*t2+1], qh[kc], &kh[2], s[2*t2+1]);
                mma16816(s[2*t2+1], qh[kc], &kl[2], s[2*t2+1]);
                mma16816(s[2*t2+1], ql[kc], &kh[2], s[2*t2+1]);
            }
        }

        // ---- online softmax (rows: lane>>2 and +8) ----
        float mx0 = -1e30f, mx1 = -1e30f;
        #pragma unroll
        for (int j = 0; j < 8; j++) {
            mx0 = fmaxf(mx0, fmaxf(s[j][0], s[j][1]));
            mx1 = fmaxf(mx1, fmaxf(s[j][2], s[j][3]));
        }
        mx0 = fmaxf(mx0, __shfl_xor_sync(0xffffffffu, mx0, 1));
        mx0 = fmaxf(mx0, __shfl_xor_sync(0xffffffffu, mx0, 2));
        mx1 = fmaxf(mx1, __shfl_xor_sync(0xffffffffu, mx1, 1));
        mx1 = fmaxf(mx1, __shfl_xor_sync(0xffffffffu, mx1, 2));
        float mn0 = fmaxf(m0, mx0), mn1 = fmaxf(m1, mx1);
        float cr0 = fast_exp(m0 - mn0), cr1 = fast_exp(m1 - mn1);
        m0 = mn0; m1 = mn1;
        float rs0 = 0.f, rs1 = 0.f;
        #pragma unroll
        for (int j = 0; j < 8; j++) {
            s[j][0] = fast_exp(s[j][0] - mn0); rs0 += s[j][0];
            s[j][1] = fast_exp(s[j][1] - mn0); rs0 += s[j][1];
            s[j][2] = fast_exp(s[j][2] - mn1); rs1 += s[j][2];
            s[j][3] = fast_exp(s[j][3] - mn1); rs1 += s[j][3];
        }
        l0 = l0 * cr0 + rs0;
        l1 = l1 * cr1 + rs1;
        #pragma unroll
        for (int u = 0; u < 8; u++) {
            oacc[u][0] *= cr0; oacc[u][1] *= cr0;
            oacc[u][2] *= cr1; oacc[u][3] *= cr1;
        }

        // ---- O += P V (3x comp); P packed reg->reg via C->A layout identity ----
        #pragma unroll
        for (int t2 = 0; t2 < 4; t2++) {
            uint32_t pha[4], pla[4];
            split2(s[2*t2][0],   s[2*t2][1],   pha[0], pla[0]);
            split2(s[2*t2][2],   s[2*t2][3],   pha[1], pla[1]);
            split2(s[2*t2+1][0], s[2*t2+1][1], pha[2], pla[2]);
            split2(s[2*t2+1][2], s[2*t2+1][3], pha[3], pla[3]);
            #pragma unroll
            for (int u = 0; u < 4; u++) {
                uint32_t vh[4], vl[4];
                uint32_t va = (uint32_t)(((16*t2 + ((lane>>3)&1)*8 + (lane&7)) * LDT
                              + u*16 + (lane>>4)*8) * 2);
                ldsm4t(vh, vhb + va);
                ldsm4t(vl, vlb + va);
                mma16816(oacc[2*u],   pha, &vh[0], oacc[2*u]);
                mma16816(oacc[2*u],   pha, &vl[0], oacc[2*u]);
                mma16816(oacc[2*u],   pla, &vh[0], oacc[2*u]);
                mma16816(oacc[2*u+1], pha, &vh[2], oacc[2*u+1]);
                mma16816(oacc[2*u+1], pha, &vl[2], oacc[2*u+1]);
                mma16816(oacc[2*u+1], pla, &vh[2], oacc[2*u+1]);
            }
        }
    }

    // ---- epilogue: normalize, write bf16 hi/lo ----
    l0 += __shfl_xor_sync(0xffffffffu, l0, 1);
    l0 += __shfl_xor_sync(0xffffffffu, l0, 2);
    l1 += __shfl_xor_sync(0xffffffffu, l1, 1);
    l1 += __shfl_xor_sync(0xffffffffu, l1, 2);
    float inv0 = 1.f / l0, inv1 = 1.f / l1;
    int tok0 = b*SEQ + q0 + warp*16 + (lane >> 2);
    int tok1 = tok0 + 8;
    int colb = h*HDM + (lane & 3) * 2;
    #pragma unroll
    for (int u = 0; u < 8; u++) {
        int col = colb + 8*u;
        uint32_t hh, ll;
        split2(oacc[u][0]*inv0, oacc[u][1]*inv0, hh, ll);
        *(uint32_t*)&Oh_g[(size_t)tok0*DIM + col] = hh;
        *(uint32_t*)&Ol_g[(size_t)tok0*DIM + col] = ll;
        split2(oacc[u][2]*inv1, oacc[u][3]*inv1, hh, ll);
        *(uint32_t*)&Oh_g[(size_t)tok1*DIM + col] = hh;
        *(uint32_t*)&Ol_g[(size_t)tok1*DIM + col] = ll;
    }
}

extern "C" void kernel_launch(void* const* d_in, const int* in_sizes, int n_in,
                              void* d_out, int out_size) {
    const float* query = (const float*)d_in[0];
    const float* key   = (const float*)d_in[1];
    const float* value = (const float*)d_in[2];
    const float* Wq = (const float*)d_in[3];
    const float* bq = (const float*)d_in[4];
    const float* Wk = (const float*)d_in[5];
    const float* bk = (const float*)d_in[6];
    const float* Wv = (const float*)d_in[7];
    const float* bv = (const float*)d_in[8];
    const float* Wo = (const float*)d_in[9];
    const float* bo = (const float*)d_in[10];
    float* out = (float*)d_out;

    __nv_bfloat16 *i0h,*i0l,*i1h,*i1l,*i2h,*i2l;
    __nv_bfloat16 *w0h,*w0l,*w1h,*w1l,*w2h,*w2l,*w3h,*w3l;
    __nv_bfloat16 *qh,*ql,*kh,*kl,*vh,*vl,*ath,*atl;
    cudaGetSymbolAddress((void**)&i0h, g_i0h); cudaGetSymbolAddress((void**)&i0l, g_i0l);
    cudaGetSymbolAddress((void**)&i1h, g_i1h); cudaGetSymbolAddress((void**)&i1l, g_i1l);
    cudaGetSymbolAddress((void**)&i2h, g_i2h); cudaGetSymbolAddress((void**)&i2l, g_i2l);
    cudaGetSymbolAddress((void**)&w0h, g_w0h); cudaGetSymbolAddress((void**)&w0l, g_w0l);
    cudaGetSymbolAddress((void**)&w1h, g_w1h); cudaGetSymbolAddress((void**)&w1l, g_w1l);
    cudaGetSymbolAddress((void**)&w2h, g_w2h); cudaGetSymbolAddress((void**)&w2l, g_w2l);
    cudaGetSymbolAddress((void**)&w3h, g_w3h); cudaGetSymbolAddress((void**)&w3l, g_w3l);
    cudaGetSymbolAddress((void**)&qh,  g_qh);  cudaGetSymbolAddress((void**)&ql,  g_ql);
    cudaGetSymbolAddress((void**)&kh,  g_kh);  cudaGetSymbolAddress((void**)&kl,  g_kl);
    cudaGetSymbolAddress((void**)&vh,  g_vh);  cudaGetSymbolAddress((void**)&vl,  g_vl);
    cudaGetSymbolAddress((void**)&ath, g_ath); cudaGetSymbolAddress((void**)&atl, g_atl);

    cudaFuncSetAttribute(gemm_bf3, cudaFuncAttributeMaxDynamicSharedMemorySize,
                         GEMM_SMEM);
    cudaFuncSetAttribute(flash_mma, cudaFuncAttributeMaxDynamicSharedMemorySize,
                         FLASH_SMEM);

    Split4 sa;
    sa.s[0] = query; sa.h[0] = i0h; sa.l[0] = i0l;
    sa.s[1] = key;   sa.h[1] = i1h; sa.l[1] = i1l;
    sa.s[2] = value; sa.h[2] = i2h; sa.l[2] = i2l;
    sa.s[3] = query; sa.h[3] = i0h; sa.l[3] = i0l;  // unused
    splitk<<<dim3(NTOK*DIM/1024, 1, 3), 256>>>(sa);

    Split4 sw;
    sw.s[0] = Wq; sw.h[0] = w0h; sw.l[0] = w0l;
    sw.s[1] = Wk; sw.h[1] = w1h; sw.l[1] = w1l;
    sw.s[2] = Wv; sw.h[2] = w2h; sw.l[2] = w2l;
    sw.s[3] = Wo; sw.h[3] = w3h; sw.l[3] = w3l;
    splitk<<<dim3(DIM*DIM/1024, 1, 4), 256>>>(sw);

    // QKV projections -> bf16 hi/lo (Q scaled by 1/8, exact)
    GemmArgs gqkv;
    gqkv.ah[0]=i0h; gqkv.al[0]=i0l; gqkv.wh[0]=w0h; gqkv.wl[0]=w0l; gqkv.bias[0]=bq;
    gqkv.c[0]=nullptr; gqkv.ch[0]=qh; gqkv.cl[0]=ql; gqkv.scale[0]=0.125f;
    gqkv.ah[1]=i1h; gqkv.al[1]=i1l; gqkv.wh[1]=w1h; gqkv.wl[1]=w1l; gqkv.bias[1]=bk;
    gqkv.c[1]=nullptr; gqkv.ch[1]=kh; gqkv.cl[1]=kl; gqkv.scale[1]=1.f;
    gqkv.ah[2]=i2h; gqkv.al[2]=i2l; gqkv.wh[2]=w2h; gqkv.wl[2]=w2l; gqkv.bias[2]=bv;
    gqkv.c[2]=nullptr; gqkv.ch[2]=vh; gqkv.cl[2]=vl; gqkv.scale[2]=1.f;
    gemm_bf3<<<dim3(DIM/128, NTOK/128, 3), 256, GEMM_SMEM>>>(gqkv);

    // tensor-core flash attention
    flash_mma<<<dim3(SEQ/QT, BTCH*NH), 256, FLASH_SMEM>>>(qh, ql, kh, kl, vh, vl,
                                                          ath, atl);

    // output projection -> fp32 out
    GemmArgs go;
    go.ah[0]=ath; go.al[0]=atl; go.wh[0]=w3h; go.wl[0]=w3l; go.bias[0]=bo;
    go.c[0]=out; go.ch[0]=nullptr; go.cl[0]=nullptr; go.scale[0]=1.f;
    go.ah[1]=ath; go.al[1]=atl; go.wh[1]=w3h; go.wl[1]=w3l; go.bias[1]=bo;
    go.c[1]=out; go.ch[1]=nullptr; go.cl[1]=nullptr; go.scale[1]=1.f;
    go.ah[2]=ath; go.al[2]=atl; go.wh[2]=w3h; go.wl[2]=w3l; go.bias[2]=bo;
    go.c[2]=out; go.ch[2]=nullptr; go.cl[2]=nullptr; go.scale[2]=1.f;
    gemm_bf3<<<dim3(DIM/128, NTOK/128, 1), 256, GEMM_SMEM>>>(go);
}